// round 15
// baseline (speedup 1.0000x reference)
#include <cuda_runtime.h>
#include <cuda_fp16.h>

#define NN 100000
#define NE 1600000
#define NBLK 391   // ceil(NN/256)

// ---------------- device scratch ----------------
__device__ unsigned int   gPQa[NN*32];   // half2{P,Q} rows, buffer A
__device__ unsigned int   gPQb[NN*32];   // buffer B
__device__ float          gR  [NN*32];
__device__ float          gAg [NN*32];   // init segsum accumulator (zero invariant)
__device__ unsigned short gRWh[NN*32];   // RW in half
__device__ float gWgT[1024];
__device__ float gWsT[1024];
__device__ float gMg[1024];
__device__ float gMs[1024];
__device__ int   gDeg[NN];      // zero at entry (static init / re-zeroed each call)
__device__ int   gOff[NN];
__device__ int   gOffCur[NN];
__device__ int   gPart[NBLK];
__device__ int   gPartOff[NBLK];
__device__ int2  gEdge[NE];     // {dst, ew_bits}

__device__ __forceinline__ float tanha(float x) {
    float y;
    asm("tanh.approx.f32 %0, %1;" : "=f"(y) : "f"(x));
    return y;
}

__device__ __forceinline__ void red4(float* p, float4 v) {
    unsigned long long ga = (unsigned long long)__cvta_generic_to_global((void*)p);
    asm volatile("red.global.add.v4.f32 [%0], {%1,%2,%3,%4};"
                 :: "l"(ga), "f"(v.x), "f"(v.y), "f"(v.z), "f"(v.w) : "memory");
}

__device__ __forceinline__ unsigned int packh2(float a, float b) {
    __half2 h = __floats2half2_rn(a, b);
    return *reinterpret_cast<unsigned int*>(&h);
}
__device__ __forceinline__ float2 unpackh2(unsigned int u) {
    __half2 h = *reinterpret_cast<__half2*>(&u);
    return __half22float2(h);
}

__device__ __forceinline__ unsigned int tf32r(float x) {
    unsigned int r;
    asm("cvt.rna.tf32.f32 %0, %1;" : "=r"(r) : "f"(x));
    return r;
}

// ---------------- prep ----------------
__global__ void k_prep(const float* __restrict__ Wg, const float* __restrict__ Ws,
                       const float* __restrict__ We) {
    int t = threadIdx.x;
    int i = t >> 5, j = t & 31;
    gWgT[t] = Wg[j*32 + i];
    gWsT[t] = Ws[j*32 + i];
    float mg = 0.f, ms = 0.f;
    #pragma unroll
    for (int k = 0; k < 32; k++) {
        float we = We[k*32 + j];
        mg += Wg[k*32 + i] * we;
        ms += Ws[k*32 + i] * we;
    }
    gMg[t] = mg; gMs[t] = ms;
}

// ---------------- CSR build (stream 0) ----------------
__global__ __launch_bounds__(256) void k_hist(const int* __restrict__ src) {
    int e = blockIdx.x * 256 + threadIdx.x;   // NE exact
    atomicAdd(&gDeg[__ldg(src + e)], 1);
}

__global__ __launch_bounds__(256) void k_part() {
    __shared__ int sp[256];
    int t = threadIdx.x;
    int i = blockIdx.x * 256 + t;
    int v = (i < NN) ? gDeg[i] : 0;
    sp[t] = v;
    __syncthreads();
    #pragma unroll
    for (int off = 128; off > 0; off >>= 1) {
        if (t < off) sp[t] += sp[t + off];
        __syncthreads();
    }
    if (t == 0) gPart[blockIdx.x] = sp[0];
}

__global__ void k_top() {
    __shared__ int sp[512];
    int t = threadIdx.x;
    int v = (t < NBLK) ? gPart[t] : 0;
    sp[t] = v;
    __syncthreads();
    #pragma unroll
    for (int off = 1; off < 512; off <<= 1) {
        int u = (t >= off) ? sp[t - off] : 0;
        __syncthreads();
        sp[t] += u;
        __syncthreads();
    }
    if (t < NBLK) gPartOff[t] = sp[t] - v;   // exclusive
}

__global__ __launch_bounds__(256) void k_apply() {
    __shared__ int sp[256];
    int t = threadIdx.x;
    int i = blockIdx.x * 256 + t;
    int v = (i < NN) ? gDeg[i] : 0;
    sp[t] = v;
    __syncthreads();
    #pragma unroll
    for (int off = 1; off < 256; off <<= 1) {
        int u = (t >= off) ? sp[t - off] : 0;
        __syncthreads();
        sp[t] += u;
        __syncthreads();
    }
    if (i < NN) {
        int excl = gPartOff[blockIdx.x] + sp[t] - v;
        gOff[i] = excl;
        gOffCur[i] = excl;
    }
}

__global__ __launch_bounds__(256) void k_scatter(const int* __restrict__ src,
                                                 const int* __restrict__ dst,
                                                 const float* __restrict__ ew) {
    int e = blockIdx.x * 256 + threadIdx.x;   // NE exact
    int s = __ldg(src + e);
    int pos = atomicAdd(&gOffCur[s], 1);
    gEdge[pos] = make_int2(__ldg(dst + e), __float_as_int(__ldg(ew + e)));
}

// ---------------- init path (stream B): atomics segsum, no CSR needed ----------------
__global__ __launch_bounds__(256) void k_edge_init(const float4* __restrict__ xE4,
                                                   const int* __restrict__ src) {
    int idx = blockIdx.x * blockDim.x + threadIdx.x;   // NE*8
    int e = idx >> 3, c = idx & 7;
    int s = __ldg(src + e);
    float4 v = __ldg(xE4 + idx);
    red4(gAg + (size_t)s*32 + c*4, v);
}

__global__ __launch_bounds__(256) void k_node_init(const float4* __restrict__ D4) {
    int idx = blockIdx.x * blockDim.x + threadIdx.x;   // NN*8
    float4 a = ((const float4*)gAg)[idx];
    ((float4*)gAg)[idx] = make_float4(0.f, 0.f, 0.f, 0.f);  // restore zero invariant
    float4 d = __ldg(D4 + idx);
    ((float4*)gR)[idx] = make_float4(d.x-a.x, d.y-a.y, d.z-a.z, d.w-a.w);
}

// ---------------- fused Y0 + P,Q (edge order, e<NN) ----------------
__global__ __launch_bounds__(256) void k_y0pq(const float4* __restrict__ xE4,
                                              const float* __restrict__ ew,
                                              const int* __restrict__ src,
                                              const int* __restrict__ dst,
                                              const float* __restrict__ Wg,
                                              const float* __restrict__ Ws,
                                              uint4* __restrict__ PQout) {
    __shared__ float sWg[1024], sWs[1024];
    __shared__ float sY[32][33];
    int t = threadIdx.x;
    for (int i = t; i < 1024; i += 256) { sWg[i] = __ldg(Wg + i); sWs[i] = __ldg(Ws + i); }
    int idx = blockIdx.x * 256 + t;           // NN*8
    int e = idx >> 3, c = idx & 7, el = t >> 3, k0 = c * 4;
    int s = __ldg(src + e), d = __ldg(dst + e);
    float w = __ldg(ew + e);
    float4 x = __ldg(xE4 + idx);
    float4 rs = ((const float4*)gR)[s*8 + c];
    float4 rd = ((const float4*)gR)[d*8 + c];
    sY[el][k0+0] = x.x + w*(rs.x - rd.x);
    sY[el][k0+1] = x.y + w*(rs.y - rd.y);
    sY[el][k0+2] = x.z + w*(rs.z - rd.z);
    sY[el][k0+3] = x.w + w*(rs.w - rd.w);
    __syncthreads();
    float4 p = make_float4(0,0,0,0), q = make_float4(0,0,0,0);
    #pragma unroll
    for (int k = 0; k < 32; k++) {
        float yk = sY[el][k];
        float4 wg = *(const float4*)(sWg + k*32 + k0);
        float4 ws = *(const float4*)(sWs + k*32 + k0);
        p.x += yk*wg.x; p.y += yk*wg.y; p.z += yk*wg.z; p.w += yk*wg.w;
        q.x += yk*ws.x; q.y += yk*ws.y; q.z += yk*ws.z; q.w += yk*ws.w;
    }
    uint4 hp;
    hp.x = packh2(p.x, q.x);
    hp.y = packh2(p.y, q.y);
    hp.z = packh2(p.z, q.z);
    hp.w = packh2(p.w, q.w);
    PQout[idx] = hp;
}

// ---------------- main edge pass (R12 form) ----------------
__global__ __launch_bounds__(256) void k_edge_csr(const unsigned int* __restrict__ PQh,
                                                  const float* __restrict__ D,
                                                  const float* __restrict__ We,
                                                  float* __restrict__ outR,
                                                  int last) {
    int wid = threadIdx.x >> 5, lane = threadIdx.x & 31;
    int n = blockIdx.x * 8 + wid;             // grid = NN/8 exact
    float ps = unpackh2(__ldg(PQh + (size_t)n*32 + lane)).x;
    int start = gOff[n], deg = gDeg[n];
    float ag = 0.f, as = 0.f;
    int j = 0;
    if ((start & 1) && deg > 0) {
        int2 E = __ldg(gEdge + start);
        float w = __int_as_float(E.y);
        float2 pq = unpackh2(__ldg(PQh + (size_t)E.x * 32 + lane));
        ag += tanha(w*(ps-pq.x));
        as += tanha(w*pq.y);
        j = 1;
    }
    const int4* ep4 = (const int4*)(gEdge + start + j);  // 16B aligned
    int rem = deg - j;
    int jb = 0;
    for (; jb + 8 <= rem; jb += 8) {
        int4 A0 = __ldg(ep4 + (jb >> 1));
        int4 A1 = __ldg(ep4 + (jb >> 1) + 1);
        int4 A2 = __ldg(ep4 + (jb >> 1) + 2);
        int4 A3 = __ldg(ep4 + (jb >> 1) + 3);
        unsigned int u0 = __ldg(PQh + (size_t)A0.x * 32 + lane);
        unsigned int u1 = __ldg(PQh + (size_t)A0.z * 32 + lane);
        unsigned int u2 = __ldg(PQh + (size_t)A1.x * 32 + lane);
        unsigned int u3 = __ldg(PQh + (size_t)A1.z * 32 + lane);
        unsigned int u4 = __ldg(PQh + (size_t)A2.x * 32 + lane);
        unsigned int u5 = __ldg(PQh + (size_t)A2.z * 32 + lane);
        unsigned int u6 = __ldg(PQh + (size_t)A3.x * 32 + lane);
        unsigned int u7 = __ldg(PQh + (size_t)A3.z * 32 + lane);
        float2 pq0 = unpackh2(u0), pq1 = unpackh2(u1);
        float2 pq2 = unpackh2(u2), pq3 = unpackh2(u3);
        float2 pq4 = unpackh2(u4), pq5 = unpackh2(u5);
        float2 pq6 = unpackh2(u6), pq7 = unpackh2(u7);
        float w0 = __int_as_float(A0.y), w1 = __int_as_float(A0.w);
        float w2 = __int_as_float(A1.y), w3 = __int_as_float(A1.w);
        float w4 = __int_as_float(A2.y), w5 = __int_as_float(A2.w);
        float w6 = __int_as_float(A3.y), w7 = __int_as_float(A3.w);
        float a0 = tanha(w0*(ps-pq0.x)), b0 = tanha(w0*pq0.y);
        float a1 = tanha(w1*(ps-pq1.x)), b1 = tanha(w1*pq1.y);
        float a2 = tanha(w2*(ps-pq2.x)), b2 = tanha(w2*pq2.y);
        float a3 = tanha(w3*(ps-pq3.x)), b3 = tanha(w3*pq3.y);
        float a4 = tanha(w4*(ps-pq4.x)), b4 = tanha(w4*pq4.y);
        float a5 = tanha(w5*(ps-pq5.x)), b5 = tanha(w5*pq5.y);
        float a6 = tanha(w6*(ps-pq6.x)), b6 = tanha(w6*pq6.y);
        float a7 = tanha(w7*(ps-pq7.x)), b7 = tanha(w7*pq7.y);
        ag += ((a0+a1)+(a2+a3)) + ((a4+a5)+(a6+a7));
        as += ((b0+b1)+(b2+b3)) + ((b4+b5)+(b6+b7));
    }
    for (j = start + j + jb; j < start + deg; j++) {
        int2 E = __ldg(gEdge + j);
        float w = __int_as_float(E.y);
        float2 pq = unpackh2(__ldg(PQh + (size_t)E.x * 32 + lane));
        ag += tanha(w*(ps-pq.x));
        as += tanha(w*pq.y);
    }
    // epilogue GEMM via warp shuffles
    float acc = 0.f;
    #pragma unroll
    for (int k = 0; k < 32; k++) {
        float a = __shfl_sync(0xffffffffu, ag, k);
        float b = __shfl_sync(0xffffffffu, as, k);
        acc += a * __ldg(gWgT + k*32 + lane) + b * __ldg(gWsT + k*32 + lane);
    }
    float r = __ldg(D + n*32 + lane) - acc;
    gR[n*32 + lane] = r;
    if (last) {
        outR[n*32 + lane] = r;
        float rw = 0.f;
        #pragma unroll
        for (int k = 0; k < 32; k++) {
            float rk = __shfl_sync(0xffffffffu, r, k);
            rw += rk * __ldg(We + k*32 + lane);
        }
        gRWh[n*32 + lane] = __half_as_ushort(__float2half_rn(rw));
        if (lane == 0) gDeg[n] = 0;   // restore zero invariant for next replay
    }
}

// ---------------- fused Zref + P,Q for next iter ----------------
__global__ __launch_bounds__(256) void k_zpq(const float* __restrict__ ew,
                                             const int* __restrict__ src,
                                             const int* __restrict__ dst,
                                             const float* __restrict__ Wg,
                                             const float* __restrict__ Ws,
                                             const uint4* __restrict__ PQin,
                                             uint4* __restrict__ PQout) {
    __shared__ float sWgT[1024], sWsT[1024], sWg[1024], sWs[1024];
    __shared__ float sA[32][33], sB[32][33], sY[32][33];
    int t = threadIdx.x;
    for (int i = t; i < 1024; i += 256) {
        sWgT[i] = gWgT[i]; sWsT[i] = gWsT[i];
        sWg[i] = __ldg(Wg + i); sWs[i] = __ldg(Ws + i);
    }
    int idx = blockIdx.x * 256 + t;           // NN*8
    int e = idx >> 3, c = idx & 7, el = t >> 3, k0 = c * 4;
    int s = __ldg(src + e), d = __ldg(dst + e);
    float w = __ldg(ew + e);
    uint4 hs = __ldg(PQin + s*8 + c);
    uint4 hd = __ldg(PQin + d*8 + c);
    float2 s0 = unpackh2(hs.x), s1 = unpackh2(hs.y), s2 = unpackh2(hs.z), s3 = unpackh2(hs.w);
    float2 d0 = unpackh2(hd.x), d1 = unpackh2(hd.y), d2 = unpackh2(hd.z), d3 = unpackh2(hd.w);
    sA[el][k0+0] = tanha(w*(s0.x - d0.x));
    sA[el][k0+1] = tanha(w*(s1.x - d1.x));
    sA[el][k0+2] = tanha(w*(s2.x - d2.x));
    sA[el][k0+3] = tanha(w*(s3.x - d3.x));
    sB[el][k0+0] = tanha(w*d0.y);
    sB[el][k0+1] = tanha(w*d1.y);
    sB[el][k0+2] = tanha(w*d2.y);
    sB[el][k0+3] = tanha(w*d3.y);
    float4 rs = ((const float4*)gR)[s*8 + c];
    float4 rd = ((const float4*)gR)[d*8 + c];
    __syncthreads();
    float4 acc;
    acc.x = w*(rs.x-rd.x); acc.y = w*(rs.y-rd.y);
    acc.z = w*(rs.z-rd.z); acc.w = w*(rs.w-rd.w);
    #pragma unroll
    for (int k = 0; k < 32; k++) {
        float ak = sA[el][k], bk = sB[el][k];
        float4 wg = *(const float4*)(sWgT + k*32 + k0);
        float4 ws = *(const float4*)(sWsT + k*32 + k0);
        acc.x += ak*wg.x + bk*ws.x;
        acc.y += ak*wg.y + bk*ws.y;
        acc.z += ak*wg.z + bk*ws.z;
        acc.w += ak*wg.w + bk*ws.w;
    }
    __syncthreads();
    sY[el][k0+0]=acc.x; sY[el][k0+1]=acc.y; sY[el][k0+2]=acc.z; sY[el][k0+3]=acc.w;
    __syncthreads();
    float4 p = make_float4(0,0,0,0), q = make_float4(0,0,0,0);
    #pragma unroll
    for (int k = 0; k < 32; k++) {
        float yk = sY[el][k];
        float4 wg = *(const float4*)(sWg + k*32 + k0);
        float4 ws = *(const float4*)(sWs + k*32 + k0);
        p.x += yk*wg.x; p.y += yk*wg.y; p.z += yk*wg.z; p.w += yk*wg.w;
        q.x += yk*ws.x; q.y += yk*ws.y; q.z += yk*ws.z; q.w += yk*ws.w;
    }
    uint4 hp;
    hp.x = packh2(p.x, q.x);
    hp.y = packh2(p.y, q.y);
    hp.z = packh2(p.z, q.z);
    hp.w = packh2(p.w, q.w);
    PQout[idx] = hp;
}

// ---------------- Xref only: tensor-core tf32 MMA (overlaps with edge pass #3) ----------------
__global__ __launch_bounds__(256) void k_xref(const float* __restrict__ ew,
                                              const int* __restrict__ src,
                                              const int* __restrict__ dst,
                                              const uint4* __restrict__ PQin,
                                              float4* __restrict__ outXref) {
    __shared__ float sT[128 * 68];
    __shared__ float sM[64 * 40];
    float* sOut = sT;

    int t = threadIdx.x;
    int lane = t & 31, w = t >> 5;

    for (int i = t; i < 2048; i += 256) {
        int k = i >> 5, n = i & 31;
        float v = (k < 32) ? gMg[k*32 + n] : gMs[(k-32)*32 + n];
        *(unsigned int*)(sM + k*40 + n) = tf32r(v);
    }

    int ebase = blockIdx.x * 128;
    #pragma unroll
    for (int r = 0; r < 4; r++) {
        int el = r*32 + (t >> 3);
        int c  = t & 7;
        int e  = ebase + el;
        int s = __ldg(src + e), d = __ldg(dst + e);
        float wgt = __ldg(ew + e);
        uint4 hs = __ldg(PQin + s*8 + c);
        uint4 hd = __ldg(PQin + d*8 + c);
        float2 s0 = unpackh2(hs.x), s1 = unpackh2(hs.y), s2 = unpackh2(hs.z), s3 = unpackh2(hs.w);
        float2 d0 = unpackh2(hd.x), d1 = unpackh2(hd.y), d2 = unpackh2(hd.z), d3 = unpackh2(hd.w);
        uint4 tg, ts;
        tg.x = tf32r(tanha(wgt*(s0.x - d0.x)));
        tg.y = tf32r(tanha(wgt*(s1.x - d1.x)));
        tg.z = tf32r(tanha(wgt*(s2.x - d2.x)));
        tg.w = tf32r(tanha(wgt*(s3.x - d3.x)));
        ts.x = tf32r(tanha(wgt*d0.y));
        ts.y = tf32r(tanha(wgt*d1.y));
        ts.z = tf32r(tanha(wgt*d2.y));
        ts.w = tf32r(tanha(wgt*d3.y));
        *(uint4*)(sT + el*68 + c*4)      = tg;
        *(uint4*)(sT + el*68 + 32 + c*4) = ts;
    }
    __syncthreads();

    float dacc[4][4];
    #pragma unroll
    for (int nt = 0; nt < 4; nt++)
        #pragma unroll
        for (int i = 0; i < 4; i++) dacc[nt][i] = 0.f;

    int g = lane >> 2;
    int tc = lane & 3;
    const float* aRow0 = sT + (w*16 + g)     * 68;
    const float* aRow1 = sT + (w*16 + g + 8) * 68;
    #pragma unroll
    for (int kk = 0; kk < 16; kk++) {
        int k0 = kk * 4;
        unsigned int a0 = *(const unsigned int*)(aRow0 + k0 + tc);
        unsigned int a1 = *(const unsigned int*)(aRow1 + k0 + tc);
        #pragma unroll
        for (int nt = 0; nt < 4; nt++) {
            unsigned int b0 = *(const unsigned int*)(sM + (k0 + tc)*40 + nt*8 + g);
            asm("mma.sync.aligned.m16n8k4.row.col.f32.tf32.tf32.f32 "
                "{%0,%1,%2,%3}, {%4,%5}, {%6}, {%0,%1,%2,%3};"
                : "+f"(dacc[nt][0]), "+f"(dacc[nt][1]),
                  "+f"(dacc[nt][2]), "+f"(dacc[nt][3])
                : "r"(a0), "r"(a1), "r"(b0));
        }
    }
    __syncthreads();

    #pragma unroll
    for (int nt = 0; nt < 4; nt++) {
        int col = nt*8 + tc*2;
        *(float2*)(sOut + (w*16 + g)*36 + col)     = make_float2(dacc[nt][0], dacc[nt][1]);
        *(float2*)(sOut + (w*16 + g + 8)*36 + col) = make_float2(dacc[nt][2], dacc[nt][3]);
    }
    __syncthreads();

    #pragma unroll
    for (int r = 0; r < 4; r++) {
        int el = r*32 + (t >> 3);
        int c  = t & 7;
        int e  = ebase + el;
        outXref[(size_t)e*8 + c] = *(const float4*)(sOut + el*36 + c*4);
    }
}

// ---------------- X = Xref + w*(RW[s]-RW[d]) (after edge#3 + k_xref join) ----------------
__global__ __launch_bounds__(256) void k_x(const float* __restrict__ ew,
                                           const int* __restrict__ src,
                                           const int* __restrict__ dst,
                                           const unsigned short* __restrict__ RWh,
                                           const float4* __restrict__ inXref,
                                           float4* __restrict__ outX) {
    int idx = blockIdx.x * blockDim.x + threadIdx.x;   // NE*8
    int e = idx >> 3, c = idx & 7;
    int s = __ldg(src + e), d = __ldg(dst + e);
    float w = __ldg(ew + e);
    float4 xr = __ldg(inXref + idx);
    uint2 rs2 = __ldg((const uint2*)(RWh + (size_t)s*32) + c);
    uint2 rd2 = __ldg((const uint2*)(RWh + (size_t)d*32) + c);
    float2 ra0 = unpackh2(rs2.x), ra1 = unpackh2(rs2.y);
    float2 rb0 = unpackh2(rd2.x), rb1 = unpackh2(rd2.y);
    float4 x;
    x.x = xr.x + w*(ra0.x - rb0.x);
    x.y = xr.y + w*(ra0.y - rb0.y);
    x.z = xr.z + w*(ra1.x - rb1.x);
    x.w = xr.w + w*(ra1.y - rb1.y);
    outX[idx] = x;
}

// ---------------- launch ----------------
extern "C" void kernel_launch(void* const* d_in, const int* in_sizes, int n_in,
                              void* d_out, int out_size) {
    const float* D  = (const float*)d_in[0];
    const float* xE = (const float*)d_in[1];
    const float* ew = (const float*)d_in[2];
    const float* Wg = (const float*)d_in[3];
    const float* Ws = (const float*)d_in[4];
    const float* We = (const float*)d_in[5];
    const int* eidx = (const int*)d_in[6];
    const int* src = eidx;
    const int* dst = eidx + NE;
    float* out = (float*)d_out;
    float4* outX    = (float4*)out;
    float4* outXref = (float4*)(out + (size_t)NE * 32);
    float*  outR    = out + (size_t)2 * NE * 32;

    static unsigned int *PQa = nullptr, *PQb = nullptr;
    static unsigned short *RWh = nullptr;
    static cudaStream_t sB = nullptr;
    static cudaEvent_t evFork = nullptr, evJoin = nullptr;
    static cudaEvent_t evFork2 = nullptr, evJoin2 = nullptr;
    if (!PQa) {
        cudaGetSymbolAddress((void**)&PQa, gPQa);
        cudaGetSymbolAddress((void**)&PQb, gPQb);
        cudaGetSymbolAddress((void**)&RWh, gRWh);
        cudaStreamCreateWithFlags(&sB, cudaStreamNonBlocking);
        cudaEventCreateWithFlags(&evFork, cudaEventDisableTiming);
        cudaEventCreateWithFlags(&evJoin, cudaEventDisableTiming);
        cudaEventCreateWithFlags(&evFork2, cudaEventDisableTiming);
        cudaEventCreateWithFlags(&evJoin2, cudaEventDisableTiming);
    }

    const int BN = 256;
    const int gN8 = NN * 8 / BN;    // 3125
    const int gE  = NE / BN;        // 6250
    const int gE8 = NE * 8 / BN;    // 50000
    const int gNW = NN / 8;         // 12500
    const int gEO = NE / 128;       // 12500

    // stream 0: prep, then fork
    k_prep<<<1, 1024>>>(Wg, Ws, We);
    cudaEventRecord(evFork, 0);
    cudaStreamWaitEvent(sB, evFork, 0);

    // stream B: init path (no CSR dependency)
    k_edge_init<<<gE8, BN, 0, sB>>>((const float4*)xE, src);
    k_node_init<<<gN8, BN, 0, sB>>>((const float4*)D);
    k_y0pq<<<gN8, BN, 0, sB>>>((const float4*)xE, ew, src, dst, Wg, Ws, (uint4*)PQa);
    cudaEventRecord(evJoin, sB);

    // stream 0: CSR build (concurrent with stream B)
    k_hist<<<gE, BN>>>(src);
    k_part<<<NBLK, BN>>>();
    k_top<<<1, 512>>>();
    k_apply<<<NBLK, BN>>>();
    k_scatter<<<gE, BN>>>(src, dst, ew);

    // join: edge passes need both CSR (stream 0) and PQa/gR (stream B)
    cudaStreamWaitEvent(0, evJoin, 0);

    k_edge_csr<<<gNW, BN>>>(PQa, D, We, outR, 0);
    k_zpq<<<gN8, BN>>>(ew, src, dst, Wg, Ws, (const uint4*)PQa, (uint4*)PQb);
    k_edge_csr<<<gNW, BN>>>(PQb, D, We, outR, 0);
    k_zpq<<<gN8, BN>>>(ew, src, dst, Wg, Ws, (const uint4*)PQb, (uint4*)PQa);

    // fork 2: k_xref (needs only PQa) overlaps with edge pass #3
    cudaEventRecord(evFork2, 0);
    cudaStreamWaitEvent(sB, evFork2, 0);
    k_xref<<<gEO, BN, 0, sB>>>(ew, src, dst, (const uint4*)PQa, outXref);
    cudaEventRecord(evJoin2, sB);

    k_edge_csr<<<gNW, BN>>>(PQa, D, We, outR, 1);

    // join 2: k_x needs RWh (stream 0) and outXref (stream B)
    cudaStreamWaitEvent(0, evJoin2, 0);
    k_x<<<gE8, BN>>>(ew, src, dst, RWh, (const float4*)outXref, outX);
}

// round 16
// speedup vs baseline: 1.2064x; 1.2064x over previous
#include <cuda_runtime.h>
#include <cuda_fp16.h>

#define NN 100000
#define NE 1600000
#define NBLK 391   // ceil(NN/256)

// ---------------- device scratch ----------------
__device__ unsigned int   gPQa[NN*32];   // half2{P,Q} rows, buffer A
__device__ unsigned int   gPQb[NN*32];   // buffer B
__device__ float          gR  [NN*32];
__device__ float          gAg [NN*32];   // init segsum accumulator (zero invariant)
__device__ unsigned short gRWh[NN*32];   // RW in half
__device__ float gWgT[1024];
__device__ float gWsT[1024];
__device__ float gMg[1024];
__device__ float gMs[1024];
__device__ int   gDeg[NN];      // zero at entry (static init / re-zeroed each call)
__device__ int   gOff[NN];
__device__ int   gOffCur[NN];
__device__ int   gPart[NBLK];
__device__ int   gPartOff[NBLK];
__device__ int2  gEdge[NE];     // {dst, ew_bits}

__device__ __forceinline__ float tanha(float x) {
    float y;
    asm("tanh.approx.f32 %0, %1;" : "=f"(y) : "f"(x));
    return y;
}

__device__ __forceinline__ void red4(float* p, float4 v) {
    unsigned long long ga = (unsigned long long)__cvta_generic_to_global((void*)p);
    asm volatile("red.global.add.v4.f32 [%0], {%1,%2,%3,%4};"
                 :: "l"(ga), "f"(v.x), "f"(v.y), "f"(v.z), "f"(v.w) : "memory");
}

__device__ __forceinline__ unsigned int packh2(float a, float b) {
    __half2 h = __floats2half2_rn(a, b);
    return *reinterpret_cast<unsigned int*>(&h);
}
__device__ __forceinline__ float2 unpackh2(unsigned int u) {
    __half2 h = *reinterpret_cast<__half2*>(&u);
    return __half22float2(h);
}

__device__ __forceinline__ unsigned int tf32r(float x) {
    unsigned int r;
    asm("cvt.rna.tf32.f32 %0, %1;" : "=r"(r) : "f"(x));
    return r;
}

// ---------------- prep ----------------
__global__ void k_prep(const float* __restrict__ Wg, const float* __restrict__ Ws,
                       const float* __restrict__ We) {
    int t = threadIdx.x;
    int i = t >> 5, j = t & 31;
    gWgT[t] = Wg[j*32 + i];
    gWsT[t] = Ws[j*32 + i];
    float mg = 0.f, ms = 0.f;
    #pragma unroll
    for (int k = 0; k < 32; k++) {
        float we = We[k*32 + j];
        mg += Wg[k*32 + i] * we;
        ms += Ws[k*32 + i] * we;
    }
    gMg[t] = mg; gMs[t] = ms;
}

// ---------------- CSR build (stream 0) ----------------
__global__ __launch_bounds__(256) void k_hist(const int* __restrict__ src) {
    int e = blockIdx.x * 256 + threadIdx.x;   // NE exact
    atomicAdd(&gDeg[__ldg(src + e)], 1);
}

__global__ __launch_bounds__(256) void k_part() {
    __shared__ int sp[256];
    int t = threadIdx.x;
    int i = blockIdx.x * 256 + t;
    int v = (i < NN) ? gDeg[i] : 0;
    sp[t] = v;
    __syncthreads();
    #pragma unroll
    for (int off = 128; off > 0; off >>= 1) {
        if (t < off) sp[t] += sp[t + off];
        __syncthreads();
    }
    if (t == 0) gPart[blockIdx.x] = sp[0];
}

__global__ void k_top() {
    __shared__ int sp[512];
    int t = threadIdx.x;
    int v = (t < NBLK) ? gPart[t] : 0;
    sp[t] = v;
    __syncthreads();
    #pragma unroll
    for (int off = 1; off < 512; off <<= 1) {
        int u = (t >= off) ? sp[t - off] : 0;
        __syncthreads();
        sp[t] += u;
        __syncthreads();
    }
    if (t < NBLK) gPartOff[t] = sp[t] - v;   // exclusive
}

__global__ __launch_bounds__(256) void k_apply() {
    __shared__ int sp[256];
    int t = threadIdx.x;
    int i = blockIdx.x * 256 + t;
    int v = (i < NN) ? gDeg[i] : 0;
    sp[t] = v;
    __syncthreads();
    #pragma unroll
    for (int off = 1; off < 256; off <<= 1) {
        int u = (t >= off) ? sp[t - off] : 0;
        __syncthreads();
        sp[t] += u;
        __syncthreads();
    }
    if (i < NN) {
        int excl = gPartOff[blockIdx.x] + sp[t] - v;
        gOff[i] = excl;
        gOffCur[i] = excl;
    }
}

__global__ __launch_bounds__(256) void k_scatter(const int* __restrict__ src,
                                                 const int* __restrict__ dst,
                                                 const float* __restrict__ ew) {
    int e = blockIdx.x * 256 + threadIdx.x;   // NE exact
    int s = __ldg(src + e);
    int pos = atomicAdd(&gOffCur[s], 1);
    gEdge[pos] = make_int2(__ldg(dst + e), __float_as_int(__ldg(ew + e)));
}

// ---------------- init path (stream B): atomics segsum, no CSR needed ----------------
__global__ __launch_bounds__(256) void k_edge_init(const float4* __restrict__ xE4,
                                                   const int* __restrict__ src) {
    int idx = blockIdx.x * blockDim.x + threadIdx.x;   // NE*8
    int e = idx >> 3, c = idx & 7;
    int s = __ldg(src + e);
    float4 v = __ldg(xE4 + idx);
    red4(gAg + (size_t)s*32 + c*4, v);
}

__global__ __launch_bounds__(256) void k_node_init(const float4* __restrict__ D4) {
    int idx = blockIdx.x * blockDim.x + threadIdx.x;   // NN*8
    float4 a = ((const float4*)gAg)[idx];
    ((float4*)gAg)[idx] = make_float4(0.f, 0.f, 0.f, 0.f);  // restore zero invariant
    float4 d = __ldg(D4 + idx);
    ((float4*)gR)[idx] = make_float4(d.x-a.x, d.y-a.y, d.z-a.z, d.w-a.w);
}

// ---------------- fused Y0 + P,Q (edge order, e<NN) ----------------
__global__ __launch_bounds__(256) void k_y0pq(const float4* __restrict__ xE4,
                                              const float* __restrict__ ew,
                                              const int* __restrict__ src,
                                              const int* __restrict__ dst,
                                              const float* __restrict__ Wg,
                                              const float* __restrict__ Ws,
                                              uint4* __restrict__ PQout) {
    __shared__ float sWg[1024], sWs[1024];
    __shared__ float sY[32][33];
    int t = threadIdx.x;
    for (int i = t; i < 1024; i += 256) { sWg[i] = __ldg(Wg + i); sWs[i] = __ldg(Ws + i); }
    int idx = blockIdx.x * 256 + t;           // NN*8
    int e = idx >> 3, c = idx & 7, el = t >> 3, k0 = c * 4;
    int s = __ldg(src + e), d = __ldg(dst + e);
    float w = __ldg(ew + e);
    float4 x = __ldg(xE4 + idx);
    float4 rs = ((const float4*)gR)[s*8 + c];
    float4 rd = ((const float4*)gR)[d*8 + c];
    sY[el][k0+0] = x.x + w*(rs.x - rd.x);
    sY[el][k0+1] = x.y + w*(rs.y - rd.y);
    sY[el][k0+2] = x.z + w*(rs.z - rd.z);
    sY[el][k0+3] = x.w + w*(rs.w - rd.w);
    __syncthreads();
    float4 p = make_float4(0,0,0,0), q = make_float4(0,0,0,0);
    #pragma unroll
    for (int k = 0; k < 32; k++) {
        float yk = sY[el][k];
        float4 wg = *(const float4*)(sWg + k*32 + k0);
        float4 ws = *(const float4*)(sWs + k*32 + k0);
        p.x += yk*wg.x; p.y += yk*wg.y; p.z += yk*wg.z; p.w += yk*wg.w;
        q.x += yk*ws.x; q.y += yk*ws.y; q.z += yk*ws.z; q.w += yk*ws.w;
    }
    uint4 hp;
    hp.x = packh2(p.x, q.x);
    hp.y = packh2(p.y, q.y);
    hp.z = packh2(p.z, q.z);
    hp.w = packh2(p.w, q.w);
    PQout[idx] = hp;
}

// ---------------- main edge pass (R12 form) ----------------
__global__ __launch_bounds__(256) void k_edge_csr(const unsigned int* __restrict__ PQh,
                                                  const float* __restrict__ D,
                                                  const float* __restrict__ We,
                                                  float* __restrict__ outR,
                                                  int last) {
    int wid = threadIdx.x >> 5, lane = threadIdx.x & 31;
    int n = blockIdx.x * 8 + wid;             // grid = NN/8 exact
    float ps = unpackh2(__ldg(PQh + (size_t)n*32 + lane)).x;
    int start = gOff[n], deg = gDeg[n];
    float ag = 0.f, as = 0.f;
    int j = 0;
    if ((start & 1) && deg > 0) {
        int2 E = __ldg(gEdge + start);
        float w = __int_as_float(E.y);
        float2 pq = unpackh2(__ldg(PQh + (size_t)E.x * 32 + lane));
        ag += tanha(w*(ps-pq.x));
        as += tanha(w*pq.y);
        j = 1;
    }
    const int4* ep4 = (const int4*)(gEdge + start + j);  // 16B aligned
    int rem = deg - j;
    int jb = 0;
    for (; jb + 8 <= rem; jb += 8) {
        int4 A0 = __ldg(ep4 + (jb >> 1));
        int4 A1 = __ldg(ep4 + (jb >> 1) + 1);
        int4 A2 = __ldg(ep4 + (jb >> 1) + 2);
        int4 A3 = __ldg(ep4 + (jb >> 1) + 3);
        unsigned int u0 = __ldg(PQh + (size_t)A0.x * 32 + lane);
        unsigned int u1 = __ldg(PQh + (size_t)A0.z * 32 + lane);
        unsigned int u2 = __ldg(PQh + (size_t)A1.x * 32 + lane);
        unsigned int u3 = __ldg(PQh + (size_t)A1.z * 32 + lane);
        unsigned int u4 = __ldg(PQh + (size_t)A2.x * 32 + lane);
        unsigned int u5 = __ldg(PQh + (size_t)A2.z * 32 + lane);
        unsigned int u6 = __ldg(PQh + (size_t)A3.x * 32 + lane);
        unsigned int u7 = __ldg(PQh + (size_t)A3.z * 32 + lane);
        float2 pq0 = unpackh2(u0), pq1 = unpackh2(u1);
        float2 pq2 = unpackh2(u2), pq3 = unpackh2(u3);
        float2 pq4 = unpackh2(u4), pq5 = unpackh2(u5);
        float2 pq6 = unpackh2(u6), pq7 = unpackh2(u7);
        float w0 = __int_as_float(A0.y), w1 = __int_as_float(A0.w);
        float w2 = __int_as_float(A1.y), w3 = __int_as_float(A1.w);
        float w4 = __int_as_float(A2.y), w5 = __int_as_float(A2.w);
        float w6 = __int_as_float(A3.y), w7 = __int_as_float(A3.w);
        float a0 = tanha(w0*(ps-pq0.x)), b0 = tanha(w0*pq0.y);
        float a1 = tanha(w1*(ps-pq1.x)), b1 = tanha(w1*pq1.y);
        float a2 = tanha(w2*(ps-pq2.x)), b2 = tanha(w2*pq2.y);
        float a3 = tanha(w3*(ps-pq3.x)), b3 = tanha(w3*pq3.y);
        float a4 = tanha(w4*(ps-pq4.x)), b4 = tanha(w4*pq4.y);
        float a5 = tanha(w5*(ps-pq5.x)), b5 = tanha(w5*pq5.y);
        float a6 = tanha(w6*(ps-pq6.x)), b6 = tanha(w6*pq6.y);
        float a7 = tanha(w7*(ps-pq7.x)), b7 = tanha(w7*pq7.y);
        ag += ((a0+a1)+(a2+a3)) + ((a4+a5)+(a6+a7));
        as += ((b0+b1)+(b2+b3)) + ((b4+b5)+(b6+b7));
    }
    for (j = start + j + jb; j < start + deg; j++) {
        int2 E = __ldg(gEdge + j);
        float w = __int_as_float(E.y);
        float2 pq = unpackh2(__ldg(PQh + (size_t)E.x * 32 + lane));
        ag += tanha(w*(ps-pq.x));
        as += tanha(w*pq.y);
    }
    // epilogue GEMM via warp shuffles
    float acc = 0.f;
    #pragma unroll
    for (int k = 0; k < 32; k++) {
        float a = __shfl_sync(0xffffffffu, ag, k);
        float b = __shfl_sync(0xffffffffu, as, k);
        acc += a * __ldg(gWgT + k*32 + lane) + b * __ldg(gWsT + k*32 + lane);
    }
    float r = __ldg(D + n*32 + lane) - acc;
    gR[n*32 + lane] = r;
    if (last) {
        outR[n*32 + lane] = r;
        float rw = 0.f;
        #pragma unroll
        for (int k = 0; k < 32; k++) {
            float rk = __shfl_sync(0xffffffffu, r, k);
            rw += rk * __ldg(We + k*32 + lane);
        }
        gRWh[n*32 + lane] = __half_as_ushort(__float2half_rn(rw));
        if (lane == 0) gDeg[n] = 0;   // restore zero invariant for next replay
    }
}

// ---------------- zpq via tensor cores: Zref MMA (K=64) + PQ MMA (K=32,N=64) ----------------
// Block = 128 edges, 256 threads = 8 warps. Tail block guarded (NN % 128 != 0).
__global__ __launch_bounds__(256) void k_zpq_mma(const float* __restrict__ ew,
                                                 const int* __restrict__ src,
                                                 const int* __restrict__ dst,
                                                 const float* __restrict__ Wg,
                                                 const float* __restrict__ Ws,
                                                 const uint4* __restrict__ PQin,
                                                 unsigned int* __restrict__ PQoutU) {
    __shared__ float sT[128 * 68];     // stage1: T tile tf32 | later overlay sOut[128][36]
    __shared__ float sM[64 * 40];      // M1 = [WgT;WsT] (64x32, stride 40); later M2 (32x64, stride 72: 2304<=2560)
    __shared__ int   sSDW[128 * 3];
    float* sOut = sT;

    int t = threadIdx.x;
    int lane = t & 31, w = t >> 5;
    int g = lane >> 2, tc = lane & 3;

    // load M1 = [WgT; WsT] tf32 (stride 40)
    for (int i = t; i < 2048; i += 256) {
        int k = i >> 5, n = i & 31;
        float v = (k < 32) ? gWgT[k*32 + n] : gWsT[(k-32)*32 + n];
        *(unsigned int*)(sM + k*40 + n) = tf32r(v);
    }

    int ebase = blockIdx.x * 128;
    // stage 1: gathers + tanh -> sT (tf32)
    #pragma unroll
    for (int r = 0; r < 4; r++) {
        int el = r*32 + (t >> 3);
        int c  = t & 7;
        int e  = ebase + el;
        int valid = (e < NN);
        int s = valid ? __ldg(src + e) : 0;
        int d = valid ? __ldg(dst + e) : 0;
        float wgt = valid ? __ldg(ew + e) : 0.f;
        if (c == 0) {
            sSDW[el*3 + 0] = s;
            sSDW[el*3 + 1] = d;
            sSDW[el*3 + 2] = __float_as_int(wgt);
        }
        uint4 hs = __ldg(PQin + s*8 + c);
        uint4 hd = __ldg(PQin + d*8 + c);
        float2 s0 = unpackh2(hs.x), s1 = unpackh2(hs.y), s2 = unpackh2(hs.z), s3 = unpackh2(hs.w);
        float2 d0 = unpackh2(hd.x), d1 = unpackh2(hd.y), d2 = unpackh2(hd.z), d3 = unpackh2(hd.w);
        uint4 tg, ts;
        tg.x = tf32r(tanha(wgt*(s0.x - d0.x)));
        tg.y = tf32r(tanha(wgt*(s1.x - d1.x)));
        tg.z = tf32r(tanha(wgt*(s2.x - d2.x)));
        tg.w = tf32r(tanha(wgt*(s3.x - d3.x)));
        ts.x = tf32r(tanha(wgt*d0.y));
        ts.y = tf32r(tanha(wgt*d1.y));
        ts.z = tf32r(tanha(wgt*d2.y));
        ts.w = tf32r(tanha(wgt*d3.y));
        *(uint4*)(sT + el*68 + c*4)      = tg;
        *(uint4*)(sT + el*68 + 32 + c*4) = ts;
    }
    __syncthreads();

    // MMA1: Zref-part[16x32] per warp, K=64
    float dacc[4][4];
    #pragma unroll
    for (int nt = 0; nt < 4; nt++)
        #pragma unroll
        for (int i = 0; i < 4; i++) dacc[nt][i] = 0.f;
    {
        const float* aRow0 = sT + (w*16 + g)     * 68;
        const float* aRow1 = sT + (w*16 + g + 8) * 68;
        #pragma unroll
        for (int kk = 0; kk < 16; kk++) {
            int k0 = kk * 4;
            unsigned int a0 = *(const unsigned int*)(aRow0 + k0 + tc);
            unsigned int a1 = *(const unsigned int*)(aRow1 + k0 + tc);
            #pragma unroll
            for (int nt = 0; nt < 4; nt++) {
                unsigned int b0 = *(const unsigned int*)(sM + (k0 + tc)*40 + nt*8 + g);
                asm("mma.sync.aligned.m16n8k4.row.col.f32.tf32.tf32.f32 "
                    "{%0,%1,%2,%3}, {%4,%5}, {%6}, {%0,%1,%2,%3};"
                    : "+f"(dacc[nt][0]), "+f"(dacc[nt][1]),
                      "+f"(dacc[nt][2]), "+f"(dacc[nt][3])
                    : "r"(a0), "r"(a1), "r"(b0));
            }
        }
    }
    __syncthreads();   // all warps done with sT (MMA1 A) and sM (M1)

    // write Zref to sOut[128][36] (fp32); concurrently load M2 = [Wg | Ws] (32x64, stride 72)
    #pragma unroll
    for (int nt = 0; nt < 4; nt++) {
        int col = nt*8 + tc*2;
        *(float2*)(sOut + (w*16 + g)*36 + col)     = make_float2(dacc[nt][0], dacc[nt][1]);
        *(float2*)(sOut + (w*16 + g + 8)*36 + col) = make_float2(dacc[nt][2], dacc[nt][3]);
    }
    for (int i = t; i < 2048; i += 256) {
        int k = i >> 6, n = i & 63;   // 32 rows x 64 cols
        float v = (n < 32) ? __ldg(Wg + k*32 + n) : __ldg(Ws + k*32 + (n - 32));
        *(unsigned int*)(sM + k*72 + n) = tf32r(v);
    }
    __syncthreads();

    // stage 3: Y = Zref + w*(R[s]-R[d]); convert to tf32 in place
    #pragma unroll
    for (int r = 0; r < 4; r++) {
        int el = r*32 + (t >> 3);
        int c  = t & 7;
        int s = sSDW[el*3 + 0];
        int d = sSDW[el*3 + 1];
        float wgt = __int_as_float(sSDW[el*3 + 2]);
        float4 zr = *(const float4*)(sOut + el*36 + c*4);
        float4 rs = ((const float4*)gR)[s*8 + c];
        float4 rd = ((const float4*)gR)[d*8 + c];
        uint4 yv;
        yv.x = tf32r(zr.x + wgt*(rs.x - rd.x));
        yv.y = tf32r(zr.y + wgt*(rs.y - rd.y));
        yv.z = tf32r(zr.z + wgt*(rs.z - rd.z));
        yv.w = tf32r(zr.w + wgt*(rs.w - rd.w));
        *(uint4*)(sOut + el*36 + c*4) = yv;
    }
    __syncthreads();

    // MMA2: PQ[16x64] per warp = Y[16x32] @ M2[32x64]; 8 n-tiles, K=32
    float d2[8][4];
    #pragma unroll
    for (int nt = 0; nt < 8; nt++)
        #pragma unroll
        for (int i = 0; i < 4; i++) d2[nt][i] = 0.f;
    {
        const float* aRow0 = sOut + (w*16 + g)     * 36;
        const float* aRow1 = sOut + (w*16 + g + 8) * 36;
        #pragma unroll
        for (int kk = 0; kk < 8; kk++) {
            int k0 = kk * 4;
            unsigned int a0 = *(const unsigned int*)(aRow0 + k0 + tc);
            unsigned int a1 = *(const unsigned int*)(aRow1 + k0 + tc);
            #pragma unroll
            for (int nt = 0; nt < 8; nt++) {
                unsigned int b0 = *(const unsigned int*)(sM + (k0 + tc)*72 + nt*8 + g);
                asm("mma.sync.aligned.m16n8k4.row.col.f32.tf32.tf32.f32 "
                    "{%0,%1,%2,%3}, {%4,%5}, {%6}, {%0,%1,%2,%3};"
                    : "+f"(d2[nt][0]), "+f"(d2[nt][1]),
                      "+f"(d2[nt][2]), "+f"(d2[nt][3])
                    : "r"(a0), "r"(a1), "r"(b0));
            }
        }
    }

    // pack half2{P[k],Q[k]} and store. P col = k (nt = k>>3), Q col = 32+k (nt = 4 + (k>>3)).
    // Thread (g,tc) holds cols nt*8 + tc*2 + {0,1} for rows (w*16+g) and (w*16+g+8).
    int e0 = ebase + w*16 + g;
    int e1 = e0 + 8;
    #pragma unroll
    for (int ntp = 0; ntp < 4; ntp++) {
        int k = ntp*8 + tc*2;
        if (e0 < NN) {
            uint2 v0;
            v0.x = packh2(d2[ntp][0], d2[ntp+4][0]);   // k
            v0.y = packh2(d2[ntp][1], d2[ntp+4][1]);   // k+1
            *(uint2*)(PQoutU + (size_t)e0*32 + k) = v0;
        }
        if (e1 < NN) {
            uint2 v1;
            v1.x = packh2(d2[ntp][2], d2[ntp+4][2]);
            v1.y = packh2(d2[ntp][3], d2[ntp+4][3]);
            *(uint2*)(PQoutU + (size_t)e1*32 + k) = v1;
        }
    }
}

// ---------------- final outputs: tensor-core (mma.sync tf32) Xref GEMM (R14 fused form) ----------------
__global__ __launch_bounds__(256) void k_out(const float* __restrict__ ew,
                                             const int* __restrict__ src,
                                             const int* __restrict__ dst,
                                             const uint4* __restrict__ PQin,
                                             const unsigned short* __restrict__ RWh,
                                             float4* __restrict__ outX,
                                             float4* __restrict__ outXref) {
    __shared__ float sT[128 * 68];
    __shared__ float sM[64 * 40];
    __shared__ int   sSDW[128 * 3];
    float* sOut = sT;

    int t = threadIdx.x;
    int lane = t & 31, w = t >> 5;

    for (int i = t; i < 2048; i += 256) {
        int k = i >> 5, n = i & 31;
        float v = (k < 32) ? gMg[k*32 + n] : gMs[(k-32)*32 + n];
        *(unsigned int*)(sM + k*40 + n) = tf32r(v);
    }

    int ebase = blockIdx.x * 128;
    #pragma unroll
    for (int r = 0; r < 4; r++) {
        int el = r*32 + (t >> 3);
        int c  = t & 7;
        int e  = ebase + el;
        int s = __ldg(src + e), d = __ldg(dst + e);
        float wgt = __ldg(ew + e);
        if (c == 0) {
            sSDW[el*3 + 0] = s;
            sSDW[el*3 + 1] = d;
            sSDW[el*3 + 2] = __float_as_int(wgt);
        }
        uint4 hs = __ldg(PQin + s*8 + c);
        uint4 hd = __ldg(PQin + d*8 + c);
        float2 s0 = unpackh2(hs.x), s1 = unpackh2(hs.y), s2 = unpackh2(hs.z), s3 = unpackh2(hs.w);
        float2 d0 = unpackh2(hd.x), d1 = unpackh2(hd.y), d2 = unpackh2(hd.z), d3 = unpackh2(hd.w);
        uint4 tg, ts;
        tg.x = tf32r(tanha(wgt*(s0.x - d0.x)));
        tg.y = tf32r(tanha(wgt*(s1.x - d1.x)));
        tg.z = tf32r(tanha(wgt*(s2.x - d2.x)));
        tg.w = tf32r(tanha(wgt*(s3.x - d3.x)));
        ts.x = tf32r(tanha(wgt*d0.y));
        ts.y = tf32r(tanha(wgt*d1.y));
        ts.z = tf32r(tanha(wgt*d2.y));
        ts.w = tf32r(tanha(wgt*d3.y));
        *(uint4*)(sT + el*68 + c*4)      = tg;
        *(uint4*)(sT + el*68 + 32 + c*4) = ts;
    }
    __syncthreads();

    float dacc[4][4];
    #pragma unroll
    for (int nt = 0; nt < 4; nt++)
        #pragma unroll
        for (int i = 0; i < 4; i++) dacc[nt][i] = 0.f;

    int g = lane >> 2;
    int tc = lane & 3;
    const float* aRow0 = sT + (w*16 + g)     * 68;
    const float* aRow1 = sT + (w*16 + g + 8) * 68;
    #pragma unroll
    for (int kk = 0; kk < 16; kk++) {
        int k0 = kk * 4;
        unsigned int a0 = *(const unsigned int*)(aRow0 + k0 + tc);
        unsigned int a1 = *(const unsigned int*)(aRow1 + k0 + tc);
        #pragma unroll
        for (int nt = 0; nt < 4; nt++) {
            unsigned int b0 = *(const unsigned int*)(sM + (k0 + tc)*40 + nt*8 + g);
            asm("mma.sync.aligned.m16n8k4.row.col.f32.tf32.tf32.f32 "
                "{%0,%1,%2,%3}, {%4,%5}, {%6}, {%0,%1,%2,%3};"
                : "+f"(dacc[nt][0]), "+f"(dacc[nt][1]),
                  "+f"(dacc[nt][2]), "+f"(dacc[nt][3])
                : "r"(a0), "r"(a1), "r"(b0));
        }
    }
    __syncthreads();

    #pragma unroll
    for (int nt = 0; nt < 4; nt++) {
        int col = nt*8 + tc*2;
        *(float2*)(sOut + (w*16 + g)*36 + col)     = make_float2(dacc[nt][0], dacc[nt][1]);
        *(float2*)(sOut + (w*16 + g + 8)*36 + col) = make_float2(dacc[nt][2], dacc[nt][3]);
    }
    __syncthreads();

    #pragma unroll
    for (int r = 0; r < 4; r++) {
        int el = r*32 + (t >> 3);
        int c  = t & 7;
        int e  = ebase + el;
        int s = sSDW[el*3 + 0];
        int d = sSDW[el*3 + 1];
        float wgt = __int_as_float(sSDW[el*3 + 2]);
        float4 xr = *(const float4*)(sOut + el*36 + c*4);
        uint2 rs2 = __ldg((const uint2*)(RWh + (size_t)s*32) + c);
        uint2 rd2 = __ldg((const uint2*)(RWh + (size_t)d*32) + c);
        float2 ra0 = unpackh2(rs2.x), ra1 = unpackh2(rs2.y);
        float2 rb0 = unpackh2(rd2.x), rb1 = unpackh2(rd2.y);
        float4 x;
        x.x = xr.x + wgt*(ra0.x - rb0.x);
        x.y = xr.y + wgt*(ra0.y - rb0.y);
        x.z = xr.z + wgt*(ra1.x - rb1.x);
        x.w = xr.w + wgt*(ra1.y - rb1.y);
        outX[(size_t)e*8 + c]    = x;
        outXref[(size_t)e*8 + c] = xr;
    }
}

// ---------------- launch ----------------
extern "C" void kernel_launch(void* const* d_in, const int* in_sizes, int n_in,
                              void* d_out, int out_size) {
    const float* D  = (const float*)d_in[0];
    const float* xE = (const float*)d_in[1];
    const float* ew = (const float*)d_in[2];
    const float* Wg = (const float*)d_in[3];
    const float* Ws = (const float*)d_in[4];
    const float* We = (const float*)d_in[5];
    const int* eidx = (const int*)d_in[6];
    const int* src = eidx;
    const int* dst = eidx + NE;
    float* out = (float*)d_out;
    float4* outX    = (float4*)out;
    float4* outXref = (float4*)(out + (size_t)NE * 32);
    float*  outR    = out + (size_t)2 * NE * 32;

    static unsigned int *PQa = nullptr, *PQb = nullptr;
    static unsigned short *RWh = nullptr;
    static cudaStream_t sB = nullptr;
    static cudaEvent_t evFork = nullptr, evJoin = nullptr;
    if (!PQa) {
        cudaGetSymbolAddress((void**)&PQa, gPQa);
        cudaGetSymbolAddress((void**)&PQb, gPQb);
        cudaGetSymbolAddress((void**)&RWh, gRWh);
        cudaStreamCreateWithFlags(&sB, cudaStreamNonBlocking);
        cudaEventCreateWithFlags(&evFork, cudaEventDisableTiming);
        cudaEventCreateWithFlags(&evJoin, cudaEventDisableTiming);
    }

    const int BN = 256;
    const int gN8 = NN * 8 / BN;          // 3125
    const int gE  = NE / BN;              // 6250
    const int gE8 = NE * 8 / BN;          // 50000
    const int gNW = NN / 8;               // 12500
    const int gEO = NE / 128;             // 12500
    const int gZ  = (NN + 127) / 128;     // 782 (tail guarded)

    // stream 0: prep, then fork
    k_prep<<<1, 1024>>>(Wg, Ws, We);
    cudaEventRecord(evFork, 0);
    cudaStreamWaitEvent(sB, evFork, 0);

    // stream B: init path (no CSR dependency)
    k_edge_init<<<gE8, BN, 0, sB>>>((const float4*)xE, src);
    k_node_init<<<gN8, BN, 0, sB>>>((const float4*)D);
    k_y0pq<<<gN8, BN, 0, sB>>>((const float4*)xE, ew, src, dst, Wg, Ws, (uint4*)PQa);
    cudaEventRecord(evJoin, sB);

    // stream 0: CSR build (concurrent with stream B)
    k_hist<<<gE, BN>>>(src);
    k_part<<<NBLK, BN>>>();
    k_top<<<1, 512>>>();
    k_apply<<<NBLK, BN>>>();
    k_scatter<<<gE, BN>>>(src, dst, ew);

    // join: edge passes need both CSR (stream 0) and PQa/gR (stream B)
    cudaStreamWaitEvent(0, evJoin, 0);

    k_edge_csr<<<gNW, BN>>>(PQa, D, We, outR, 0);
    k_zpq_mma<<<gZ, BN>>>(ew, src, dst, Wg, Ws, (const uint4*)PQa, PQb);
    k_edge_csr<<<gNW, BN>>>(PQb, D, We, outR, 0);
    k_zpq_mma<<<gZ, BN>>>(ew, src, dst, Wg, Ws, (const uint4*)PQb, PQa);
    k_edge_csr<<<gNW, BN>>>(PQa, D, We, outR, 1);
    k_out<<<gEO, BN>>>(ew, src, dst, (const uint4*)PQa, RWh, outX, outXref);
}